// round 1
// baseline (speedup 1.0000x reference)
#include <cuda_runtime.h>
#include <cstdint>

#define B_    4
#define CIN   1536
#define HIDF  1536
#define OUTF  512
#define HH    64
#define NN    4096           // 64*64
#define MROWS (B_ * NN)      // 16384

// ---------------- scratch (device globals; allocation-free) ----------------
__device__ float g_xt[(size_t)B_ * NN * CIN];   // x transposed  [B, N, C]
__device__ float g_S [(size_t)B_ * NN * CIN];   // stencil(xt)   [B, N, C]
__device__ float g_H1[(size_t)B_ * NN * HIDF];  // relu(S@W1+b1) [B, N, HID]
__device__ float g_T [(size_t)B_ * NN * HIDF];  // stencil(H1)+S [B, N, HID]
__device__ float g_or[(size_t)B_ * NN * OUTF];  // xt@Wl+bl      [B, N, OUT]
__device__ float g_of[(size_t)B_ * NN * OUTF];  // final, n-major [B, N, OUT]

// ---------------- transpose in: x [B,C,N] -> g_xt [B,N,C] -------------------
__global__ void k_tin(const float* __restrict__ x) {
    __shared__ float tile[32][33];
    int b  = blockIdx.z;
    int n0 = blockIdx.x << 5;
    int c0 = blockIdx.y << 5;
    int tx = threadIdx.x, ty = threadIdx.y;
    const float* xb = x + (size_t)b * CIN * NN;
#pragma unroll
    for (int i = ty; i < 32; i += 8)
        tile[i][tx] = xb[(size_t)(c0 + i) * NN + (n0 + tx)];
    __syncthreads();
    float* o = g_xt + (size_t)b * NN * CIN;
#pragma unroll
    for (int i = ty; i < 32; i += 8)
        o[(size_t)(n0 + i) * CIN + (c0 + tx)] = tile[tx][i];
}

// ---------------- 5-point GCN stencil (deg analytic on grid) ----------------
__device__ __forceinline__ int degat(int r, int c) {
    return 1 + (r > 0) + (r < HH - 1) + (c > 0) + (c < HH - 1);
}

template <bool ADD>
__global__ void k_stencil(const float4* __restrict__ in,
                          const float4* __restrict__ add,
                          float4* __restrict__ out) {
    const int C4 = CIN / 4;          // 384
    int n = blockIdx.x;
    int b = blockIdx.y;
    int t = threadIdx.x;             // 0..383
    int r = n >> 6, c = n & 63;
    int dg = degat(r, c);
    size_t base = (size_t)b * NN * C4;
    const float4* pin = in + base;

    float4 v  = pin[(size_t)n * C4 + t];
    float  wc = 1.0f / (float)dg;
    float4 acc = make_float4(v.x * wc, v.y * wc, v.z * wc, v.w * wc);

#define NBR(nm, dr, dc)                                          \
    {                                                            \
        int   dn = degat(r + (dr), c + (dc));                    \
        float w  = rsqrtf((float)(dg * dn));                     \
        float4 u = pin[(size_t)(nm) * C4 + t];                   \
        acc.x += u.x * w; acc.y += u.y * w;                      \
        acc.z += u.z * w; acc.w += u.w * w;                      \
    }
    if (r > 0)  NBR(n - 64, -1, 0);
    if (r < 63) NBR(n + 64, +1, 0);
    if (c > 0)  NBR(n - 1, 0, -1);
    if (c < 63) NBR(n + 1, 0, +1);
#undef NBR

    if (ADD) {
        float4 s = add[base + (size_t)n * C4 + t];
        acc.x += s.x; acc.y += s.y; acc.z += s.z; acc.w += s.w;
    }
    out[base + (size_t)n * C4 + t] = acc;
}

// ---------------- fp32 tiled GEMM: C = epi(A @ Bm + bias) -------------------
// A [MROWS x CIN] row-major, Bm [CIN x Nc] row-major.
// EPI: 0 = relu(.+bias)   1 = .+bias   2 = (.+bias) * mul
#define BM 128
#define BN 128
#define BK 16

template <int EPI>
__global__ __launch_bounds__(256) void k_gemm(
    const float* __restrict__ A, const float* __restrict__ Bm,
    const float* __restrict__ bias, const float* __restrict__ mul,
    float* __restrict__ C, int Nc)
{
    const int K = CIN;
    __shared__ float As[2][BK][BM];
    __shared__ float Bs[2][BK][BN];
    int tid = threadIdx.x;
    int tx = tid & 15, ty = tid >> 4;
    int bm = blockIdx.y * BM;
    int bn = blockIdx.x * BN;

    int a_row = tid >> 2;            // 0..63 (+64 for second half)
    int a_k   = (tid & 3) << 2;      // 0,4,8,12
    const float* Ap = A + (size_t)(bm + a_row) * K + a_k;

    int b_row = tid >> 5;            // 0..7 (+8 for second half)
    int b_col = (tid & 31) << 2;     // 0..124
    const float* Bp = Bm + (size_t)b_row * Nc + bn + b_col;

    float acc[8][8];
#pragma unroll
    for (int i = 0; i < 8; i++)
#pragma unroll
        for (int j = 0; j < 8; j++) acc[i][j] = 0.f;

    // prologue: tile 0
    float4 a0 = *(const float4*)(Ap);
    float4 a1 = *(const float4*)(Ap + (size_t)64 * K);
    float4 b0 = *(const float4*)(Bp);
    float4 b1 = *(const float4*)(Bp + (size_t)8 * Nc);
    As[0][a_k + 0][a_row] = a0.x; As[0][a_k + 1][a_row] = a0.y;
    As[0][a_k + 2][a_row] = a0.z; As[0][a_k + 3][a_row] = a0.w;
    As[0][a_k + 0][a_row + 64] = a1.x; As[0][a_k + 1][a_row + 64] = a1.y;
    As[0][a_k + 2][a_row + 64] = a1.z; As[0][a_k + 3][a_row + 64] = a1.w;
    *(float4*)&Bs[0][b_row][b_col]     = b0;
    *(float4*)&Bs[0][b_row + 8][b_col] = b1;
    __syncthreads();

    const int nK = K / BK;  // 96
    for (int kt = 0; kt < nK; kt++) {
        int cur = kt & 1;
        if (kt + 1 < nK) {
            const float* Ap2 = Ap + (kt + 1) * BK;
            a0 = *(const float4*)(Ap2);
            a1 = *(const float4*)(Ap2 + (size_t)64 * K);
            const float* Bp2 = Bp + (size_t)(kt + 1) * BK * Nc;
            b0 = *(const float4*)(Bp2);
            b1 = *(const float4*)(Bp2 + (size_t)8 * Nc);
        }
#pragma unroll
        for (int k = 0; k < BK; k++) {
            float4 av0 = *(const float4*)&As[cur][k][(ty << 2)];
            float4 av1 = *(const float4*)&As[cur][k][64 + (ty << 2)];
            float4 bv0 = *(const float4*)&Bs[cur][k][(tx << 2)];
            float4 bv1 = *(const float4*)&Bs[cur][k][64 + (tx << 2)];
            float ar[8] = {av0.x, av0.y, av0.z, av0.w, av1.x, av1.y, av1.z, av1.w};
            float br[8] = {bv0.x, bv0.y, bv0.z, bv0.w, bv1.x, bv1.y, bv1.z, bv1.w};
#pragma unroll
            for (int i = 0; i < 8; i++)
#pragma unroll
                for (int j = 0; j < 8; j++)
                    acc[i][j] = fmaf(ar[i], br[j], acc[i][j]);
        }
        if (kt + 1 < nK) {
            int nxt = cur ^ 1;
            As[nxt][a_k + 0][a_row] = a0.x; As[nxt][a_k + 1][a_row] = a0.y;
            As[nxt][a_k + 2][a_row] = a0.z; As[nxt][a_k + 3][a_row] = a0.w;
            As[nxt][a_k + 0][a_row + 64] = a1.x; As[nxt][a_k + 1][a_row + 64] = a1.y;
            As[nxt][a_k + 2][a_row + 64] = a1.z; As[nxt][a_k + 3][a_row + 64] = a1.w;
            *(float4*)&Bs[nxt][b_row][b_col]     = b0;
            *(float4*)&Bs[nxt][b_row + 8][b_col] = b1;
        }
        __syncthreads();
    }

    // epilogue
    int cn0 = bn + (tx << 2);
    int cn1 = cn0 + 64;
    float4 bb0 = *(const float4*)&bias[cn0];
    float4 bb1 = *(const float4*)&bias[cn1];
#pragma unroll
    for (int i = 0; i < 8; i++) {
        int row = bm + ((i < 4) ? ((ty << 2) + i) : (64 + (ty << 2) + i - 4));
        float4 r0 = make_float4(acc[i][0] + bb0.x, acc[i][1] + bb0.y,
                                acc[i][2] + bb0.z, acc[i][3] + bb0.w);
        float4 r1 = make_float4(acc[i][4] + bb1.x, acc[i][5] + bb1.y,
                                acc[i][6] + bb1.z, acc[i][7] + bb1.w);
        if (EPI == 0) {
            r0.x = fmaxf(r0.x, 0.f); r0.y = fmaxf(r0.y, 0.f);
            r0.z = fmaxf(r0.z, 0.f); r0.w = fmaxf(r0.w, 0.f);
            r1.x = fmaxf(r1.x, 0.f); r1.y = fmaxf(r1.y, 0.f);
            r1.z = fmaxf(r1.z, 0.f); r1.w = fmaxf(r1.w, 0.f);
        }
        if (EPI == 2) {
            float4 m0 = *(const float4*)&mul[(size_t)row * Nc + cn0];
            float4 m1 = *(const float4*)&mul[(size_t)row * Nc + cn1];
            r0.x *= m0.x; r0.y *= m0.y; r0.z *= m0.z; r0.w *= m0.w;
            r1.x *= m1.x; r1.y *= m1.y; r1.z *= m1.z; r1.w *= m1.w;
        }
        *(float4*)&C[(size_t)row * Nc + cn0] = r0;
        *(float4*)&C[(size_t)row * Nc + cn1] = r1;
    }
}

// ---------------- transpose out: g_of [B,N,OUT] -> out [B,OUT,N] ------------
__global__ void k_tout(float* __restrict__ out) {
    __shared__ float tile[32][33];
    int b  = blockIdx.z;
    int f0 = blockIdx.x << 5;
    int n0 = blockIdx.y << 5;
    int tx = threadIdx.x, ty = threadIdx.y;
    const float* src = g_of + (size_t)b * NN * OUTF;
#pragma unroll
    for (int i = ty; i < 32; i += 8)
        tile[i][tx] = src[(size_t)(n0 + i) * OUTF + (f0 + tx)];
    __syncthreads();
    float* dst = out + (size_t)b * OUTF * NN;
#pragma unroll
    for (int i = ty; i < 32; i += 8)
        dst[(size_t)(f0 + i) * NN + (n0 + tx)] = tile[tx][i];
}

// ---------------- launch ----------------------------------------------------
extern "C" void kernel_launch(void* const* d_in, const int* in_sizes, int n_in,
                              void* d_out, int out_size) {
    const float* x  = (const float*)d_in[0];
    const float* W1 = (const float*)d_in[1];
    const float* b1 = (const float*)d_in[2];
    const float* W2 = (const float*)d_in[3];
    const float* b2 = (const float*)d_in[4];
    const float* Wl = (const float*)d_in[5];
    const float* bl = (const float*)d_in[6];
    // d_in[7], d_in[8] = src, dst — grid is analytic, unused.
    float* out = (float*)d_out;

    float *p_xt, *p_S, *p_H1, *p_T, *p_or, *p_of;
    cudaGetSymbolAddress((void**)&p_xt, g_xt);
    cudaGetSymbolAddress((void**)&p_S,  g_S);
    cudaGetSymbolAddress((void**)&p_H1, g_H1);
    cudaGetSymbolAddress((void**)&p_T,  g_T);
    cudaGetSymbolAddress((void**)&p_or, g_or);
    cudaGetSymbolAddress((void**)&p_of, g_of);

    // 1. transpose x -> xt
    k_tin<<<dim3(NN / 32, CIN / 32, B_), dim3(32, 8)>>>(x);
    // 2. S = stencil(xt)
    k_stencil<false><<<dim3(NN, B_), CIN / 4>>>(
        (const float4*)p_xt, nullptr, (float4*)p_S);
    // 3. H1 = relu(S @ W1 + b1)
    k_gemm<0><<<dim3(HIDF / BN, MROWS / BM), 256>>>(
        p_S, W1, b1, nullptr, p_H1, HIDF);
    // 4. T = stencil(H1) + S
    k_stencil<true><<<dim3(NN, B_), CIN / 4>>>(
        (const float4*)p_H1, (const float4*)p_S, (float4*)p_T);
    // 5. origin = xt @ Wl + bl
    k_gemm<1><<<dim3(OUTF / BN, MROWS / BM), 256>>>(
        p_xt, Wl, bl, nullptr, p_or, OUTF);
    // 6. of = (T @ W2 + b2) * origin
    k_gemm<2><<<dim3(OUTF / BN, MROWS / BM), 256>>>(
        p_T, W2, b2, p_or, p_of, OUTF);
    // 7. transpose of -> out [B, 512, 64, 64]
    k_tout<<<dim3(OUTF / 32, NN / 32, B_), dim3(32, 8)>>>(out);
}

// round 5
// speedup vs baseline: 1.9677x; 1.9677x over previous
#include <cuda_runtime.h>
#include <cuda_bf16.h>
#include <cstdint>

#define B_    4
#define CIN   1536
#define HIDF  1536
#define OUTF  512
#define HH    64
#define NN    4096
#define MROWS (B_ * NN)      // 16384

// ---------------- GEMM tile config (HMMA mma.sync path) ---------------------
#define BMt 128
#define BNt 128
#define BKt 32
#define NKT (CIN / BKt)          // 48
#define ROWPITCH 80              // 32 bf16 = 64B data, padded to 80B (conflict-free ldmatrix)
#define ARR_BYTES (128 * ROWPITCH)   // 10240 per operand array
#define STG_BYTES (4 * ARR_BYTES)    // Ah, Al, Bh, Bl = 40960
#define NSTAGE 3
#define SMEM_GMM (NSTAGE * STG_BYTES)  // 122880

// ---------------- scratch ----------------------------------------------------
__device__ float         g_xt [(size_t)MROWS * CIN];
__device__ __nv_bfloat16 g_xth[(size_t)MROWS * CIN];
__device__ __nv_bfloat16 g_xtl[(size_t)MROWS * CIN];
__device__ __nv_bfloat16 g_Sh [(size_t)MROWS * CIN];
__device__ __nv_bfloat16 g_Sl [(size_t)MROWS * CIN];
__device__ float         g_H1 [(size_t)MROWS * HIDF];
__device__ __nv_bfloat16 g_Th [(size_t)MROWS * HIDF];
__device__ __nv_bfloat16 g_Tl [(size_t)MROWS * HIDF];
__device__ float         g_or [(size_t)MROWS * OUTF];   // origin row-major [m][f]
__device__ __nv_bfloat16 g_W1h[(size_t)HIDF * CIN];
__device__ __nv_bfloat16 g_W1l[(size_t)HIDF * CIN];
__device__ __nv_bfloat16 g_W2h[(size_t)OUTF * CIN];
__device__ __nv_bfloat16 g_W2l[(size_t)OUTF * CIN];
__device__ __nv_bfloat16 g_Wlh[(size_t)OUTF * CIN];
__device__ __nv_bfloat16 g_Wll[(size_t)OUTF * CIN];

// ---------------- helpers ----------------------------------------------------
__device__ __forceinline__ uint32_t smem_u32(const void* p) {
    uint32_t a;
    asm("{ .reg .u64 t; cvta.to.shared.u64 t, %1; cvt.u32.u64 %0, t; }" : "=r"(a) : "l"(p));
    return a;
}
__device__ __forceinline__ void cp16(uint32_t dst, const void* src) {
    asm volatile("cp.async.cg.shared.global [%0], [%1], 16;" :: "r"(dst), "l"(src));
}
#define CP_COMMIT() asm volatile("cp.async.commit_group;" ::: "memory")
#define CP_WAIT1()  asm volatile("cp.async.wait_group 1;" ::: "memory")
#define CP_WAIT0()  asm volatile("cp.async.wait_group 0;" ::: "memory")

#define LDSM4(r0, r1, r2, r3, a)                                           \
    asm volatile("ldmatrix.sync.aligned.m8n8.x4.shared.b16 {%0,%1,%2,%3}, [%4];" \
                 : "=r"(r0), "=r"(r1), "=r"(r2), "=r"(r3) : "r"(a))

#define MMA(d, a, b0, b1)                                                  \
    asm volatile("mma.sync.aligned.m16n8k16.row.col.f32.bf16.bf16.f32 "    \
                 "{%0,%1,%2,%3},{%4,%5,%6,%7},{%8,%9},{%0,%1,%2,%3};"      \
                 : "+f"((d)[0]), "+f"((d)[1]), "+f"((d)[2]), "+f"((d)[3])  \
                 : "r"((a)[0]), "r"((a)[1]), "r"((a)[2]), "r"((a)[3]),     \
                   "r"(b0), "r"(b1))

__device__ __forceinline__ void split1(float v, __nv_bfloat16& h, __nv_bfloat16& l) {
    h = __float2bfloat16_rn(v);
    l = __float2bfloat16_rn(v - __bfloat162float(h));
}

// ---------------- transpose in: x [B,C,N] -> xt fp32 + hi/lo ----------------
__global__ void k_tin(const float* __restrict__ x) {
    __shared__ float tile[32][33];
    int b = blockIdx.z, n0 = blockIdx.x << 5, c0 = blockIdx.y << 5;
    int tx = threadIdx.x, ty = threadIdx.y;
    const float* xb = x + (size_t)b * CIN * NN;
#pragma unroll
    for (int i = ty; i < 32; i += 8)
        tile[i][tx] = xb[(size_t)(c0 + i) * NN + (n0 + tx)];
    __syncthreads();
    size_t ob = (size_t)b * NN * CIN;
#pragma unroll
    for (int i = ty; i < 32; i += 8) {
        float v = tile[tx][i];
        size_t idx = ob + (size_t)(n0 + i) * CIN + (c0 + tx);
        g_xt[idx] = v;
        __nv_bfloat16 h, l; split1(v, h, l);
        g_xth[idx] = h; g_xtl[idx] = l;
    }
}

// ---------------- weight prep: W [K,Nc] -> Wt hi/lo [Nc,K] ------------------
__global__ void k_wt(const float* __restrict__ W, __nv_bfloat16* __restrict__ oh,
                     __nv_bfloat16* __restrict__ ol, int Nc) {
    __shared__ float tile[32][33];
    int n0 = blockIdx.x << 5, k0 = blockIdx.y << 5;
    int tx = threadIdx.x, ty = threadIdx.y;
#pragma unroll
    for (int i = ty; i < 32; i += 8)
        tile[i][tx] = W[(size_t)(k0 + i) * Nc + (n0 + tx)];
    __syncthreads();
#pragma unroll
    for (int i = ty; i < 32; i += 8) {
        float v = tile[tx][i];
        size_t idx = (size_t)(n0 + i) * CIN + (k0 + tx);
        __nv_bfloat16 h, l; split1(v, h, l);
        oh[idx] = h; ol[idx] = l;
    }
}

// ---------------- 5-point GCN stencil -> bf16 hi/lo -------------------------
__device__ __forceinline__ int degat(int r, int c) {
    return 1 + (r > 0) + (r < HH - 1) + (c > 0) + (c < HH - 1);
}

__global__ void k_st(const float4* __restrict__ in,
                     __nv_bfloat16* __restrict__ oh, __nv_bfloat16* __restrict__ ol) {
    const int C4 = CIN / 4;
    int n = blockIdx.x, b = blockIdx.y, t = threadIdx.x;
    int r = n >> 6, c = n & 63;
    int dg = degat(r, c);
    size_t base = (size_t)b * NN * C4;
    const float4* pin = in + base;

    float4 v = pin[(size_t)n * C4 + t];
    float wc = 1.0f / (float)dg;
    float4 acc = make_float4(v.x * wc, v.y * wc, v.z * wc, v.w * wc);
#define NBR(nm, dr, dc)                                      \
    {                                                        \
        int dn = degat(r + (dr), c + (dc));                  \
        float w = rsqrtf((float)(dg * dn));                  \
        float4 u = pin[(size_t)(nm) * C4 + t];               \
        acc.x += u.x * w; acc.y += u.y * w;                  \
        acc.z += u.z * w; acc.w += u.w * w;                  \
    }
    if (r > 0)  NBR(n - 64, -1, 0);
    if (r < 63) NBR(n + 64, +1, 0);
    if (c > 0)  NBR(n - 1, 0, -1);
    if (c < 63) NBR(n + 1, 0, +1);
#undef NBR
    __nv_bfloat16 hx, lx, hy, ly, hz, lz, hw, lw;
    split1(acc.x, hx, lx); split1(acc.y, hy, ly);
    split1(acc.z, hz, lz); split1(acc.w, hw, lw);
    uint32_t h01 = ((uint32_t)__bfloat16_as_ushort(hy) << 16) | __bfloat16_as_ushort(hx);
    uint32_t h23 = ((uint32_t)__bfloat16_as_ushort(hw) << 16) | __bfloat16_as_ushort(hz);
    uint32_t l01 = ((uint32_t)__bfloat16_as_ushort(ly) << 16) | __bfloat16_as_ushort(lx);
    uint32_t l23 = ((uint32_t)__bfloat16_as_ushort(lw) << 16) | __bfloat16_as_ushort(lz);
    size_t idx = base + (size_t)n * C4 + t;
    ((uint2*)oh)[idx] = make_uint2(h01, h23);
    ((uint2*)ol)[idx] = make_uint2(l01, l23);
}

// ---------------- HMMA split-bf16 GEMM --------------------------------------
// D[m,n] = sum_k A[m,k]*B[n,k]  (B is weight-transposed [n][k], k contiguous)
// via AhBh + AhBl + AlBh, fp32 accumulate in registers.
// EPI 0: C[m][Nc] = relu(acc+bias[n]) + aux[m][Nc]
// EPI 1: C[m][Nc] = acc + bias[n]
// EPI 2: out[(b*OUTF+n)*NN + (m&4095)] = (acc+bias[n]) * aux[m][Nc]
template <int EPI>
__global__ __launch_bounds__(256, 1) void k_gmm(
    const __nv_bfloat16* __restrict__ Ah, const __nv_bfloat16* __restrict__ Al,
    const __nv_bfloat16* __restrict__ Bh, const __nv_bfloat16* __restrict__ Bl,
    const float* __restrict__ bias, const float* __restrict__ aux,
    float* __restrict__ C, int Nc)
{
    extern __shared__ char smem[];
    uint32_t sb = smem_u32(smem);
    int tid = threadIdx.x, wid = tid >> 5, lane = tid & 31;
    int bm = blockIdx.y * BMt, bn = blockIdx.x * BNt;

    // ---- producer addressing (8 x 16B cp.async per thread per stage) ----
    const __nv_bfloat16* psrc[8];
    uint32_t pdst[8];
#pragma unroll
    for (int j = 0; j < 8; j++) {
        int cch = tid + j * 256;
        int arr = cch >> 9;          // 0:Ah 1:Al 2:Bh 3:Bl
        int rw  = (cch >> 2) & 127;
        int sl  = cch & 3;
        const __nv_bfloat16* base =
            (arr == 0) ? Ah : (arr == 1) ? Al : (arr == 2) ? Bh : Bl;
        int row0 = ((arr < 2) ? bm : bn) + rw;
        psrc[j] = base + (size_t)row0 * CIN + sl * 8;
        pdst[j] = (uint32_t)(arr * ARR_BYTES + rw * ROWPITCH + sl * 16);
    }

#define ISSUE(stg, kt)                                                     \
    {                                                                      \
        uint32_t stb_ = sb + (stg) * STG_BYTES;                            \
        _Pragma("unroll")                                                  \
        for (int j = 0; j < 8; j++)                                        \
            cp16(stb_ + pdst[j], psrc[j] + (kt) * BKt);                    \
        CP_COMMIT();                                                       \
    }

    ISSUE(0, 0);
    ISSUE(1, 1);

    // ---- consumer addressing ----
    int wm = wid & 1, wn = wid >> 1;
    uint32_t a_base = (uint32_t)((wm * 64 + (lane & 15)) * ROWPITCH + ((lane >> 4) << 4));
    uint32_t b_base = (uint32_t)(2 * ARR_BYTES +
        (wn * 32 + ((lane & 7) | ((lane >> 4) << 3))) * ROWPITCH + (((lane >> 3) & 1) << 4));

    float acc[4][4][4];
#pragma unroll
    for (int mi = 0; mi < 4; mi++)
#pragma unroll
        for (int nt = 0; nt < 4; nt++)
#pragma unroll
            for (int q = 0; q < 4; q++) acc[mi][nt][q] = 0.f;

    for (int kt = 0; kt < NKT; kt++) {
        if (kt + 1 < NKT) CP_WAIT1(); else CP_WAIT0();
        __syncthreads();
        if (kt + 2 < NKT) ISSUE((kt + 2) % NSTAGE, kt + 2);

        uint32_t st = sb + (kt % NSTAGE) * STG_BYTES;
#pragma unroll
        for (int ks = 0; ks < 2; ks++) {
            uint32_t ah[4][4], al[4][4], bh[4][2], bl[4][2];
            uint32_t ak = st + a_base + ks * 32;
#pragma unroll
            for (int mi = 0; mi < 4; mi++) {
                LDSM4(ah[mi][0], ah[mi][1], ah[mi][2], ah[mi][3], ak + mi * (16 * ROWPITCH));
                LDSM4(al[mi][0], al[mi][1], al[mi][2], al[mi][3],
                      ak + ARR_BYTES + mi * (16 * ROWPITCH));
            }
#pragma unroll
            for (int j = 0; j < 2; j++) {
                uint32_t bk = st + b_base + ks * 32 + j * (16 * ROWPITCH);
                uint32_t r0, r1, r2, r3;
                LDSM4(r0, r1, r2, r3, bk);
                bh[j * 2][0] = r0; bh[j * 2][1] = r1;
                bh[j * 2 + 1][0] = r2; bh[j * 2 + 1][1] = r3;
                LDSM4(r0, r1, r2, r3, bk + ARR_BYTES);
                bl[j * 2][0] = r0; bl[j * 2][1] = r1;
                bl[j * 2 + 1][0] = r2; bl[j * 2 + 1][1] = r3;
            }
#pragma unroll
            for (int mi = 0; mi < 4; mi++)
#pragma unroll
                for (int nt = 0; nt < 4; nt++)
                    MMA(acc[mi][nt], ah[mi], bh[nt][0], bh[nt][1]);
#pragma unroll
            for (int mi = 0; mi < 4; mi++)
#pragma unroll
                for (int nt = 0; nt < 4; nt++)
                    MMA(acc[mi][nt], ah[mi], bl[nt][0], bl[nt][1]);
#pragma unroll
            for (int mi = 0; mi < 4; mi++)
#pragma unroll
                for (int nt = 0; nt < 4; nt++)
                    MMA(acc[mi][nt], al[mi], bh[nt][0], bh[nt][1]);
        }
    }

    // ---- epilogue (register fragments, fused) ----
#pragma unroll
    for (int mi = 0; mi < 4; mi++)
#pragma unroll
        for (int nt = 0; nt < 4; nt++) {
            int m0 = bm + wm * 64 + mi * 16 + (lane >> 2);
            int n0 = bn + wn * 32 + nt * 8 + ((lane & 3) << 1);
            const float* a4 = acc[mi][nt];
            float bs0 = __ldg(&bias[n0]), bs1 = __ldg(&bias[n0 + 1]);
            size_t i0 = (size_t)m0 * Nc + n0;
            size_t i1 = (size_t)(m0 + 8) * Nc + n0;
            if (EPI == 0) {
                float2 x0 = *(const float2*)(aux + i0);
                float2 x1 = *(const float2*)(aux + i1);
                float2 o0 = make_float2(fmaxf(a4[0] + bs0, 0.f) + x0.x,
                                        fmaxf(a4[1] + bs1, 0.f) + x0.y);
                float2 o1 = make_float2(fmaxf(a4[2] + bs0, 0.f) + x1.x,
                                        fmaxf(a4[3] + bs1, 0.f) + x1.y);
                *(float2*)(C + i0) = o0;
                *(float2*)(C + i1) = o1;
            } else if (EPI == 1) {
                *(float2*)(C + i0) = make_float2(a4[0] + bs0, a4[1] + bs1);
                *(float2*)(C + i1) = make_float2(a4[2] + bs0, a4[3] + bs1);
            } else {
                float2 g0 = *(const float2*)(aux + i0);
                float2 g1 = *(const float2*)(aux + i1);
                int b0 = m0 >> 12, nn0 = m0 & (NN - 1);
                int nn1 = nn0 + 8;   // m0+8 stays in same batch (16-aligned tiles)
                C[((size_t)(b0 * OUTF + n0)) * NN + nn0]     = (a4[0] + bs0) * g0.x;
                C[((size_t)(b0 * OUTF + n0 + 1)) * NN + nn0] = (a4[1] + bs1) * g0.y;
                C[((size_t)(b0 * OUTF + n0)) * NN + nn1]     = (a4[2] + bs0) * g1.x;
                C[((size_t)(b0 * OUTF + n0 + 1)) * NN + nn1] = (a4[3] + bs1) * g1.y;
            }
        }
#undef ISSUE
}

// ---------------- launch -----------------------------------------------------
extern "C" void kernel_launch(void* const* d_in, const int* in_sizes, int n_in,
                              void* d_out, int out_size) {
    const float* x  = (const float*)d_in[0];
    const float* W1 = (const float*)d_in[1];
    const float* b1 = (const float*)d_in[2];
    const float* W2 = (const float*)d_in[3];
    const float* b2 = (const float*)d_in[4];
    const float* Wl = (const float*)d_in[5];
    const float* bl = (const float*)d_in[6];
    float* out = (float*)d_out;

    float *p_xt, *p_H1, *p_or;
    __nv_bfloat16 *p_xth, *p_xtl, *p_Sh, *p_Sl, *p_Th, *p_Tl;
    __nv_bfloat16 *p_W1h, *p_W1l, *p_W2h, *p_W2l, *p_Wlh, *p_Wll;
    cudaGetSymbolAddress((void**)&p_xt,  g_xt);
    cudaGetSymbolAddress((void**)&p_xth, g_xth);
    cudaGetSymbolAddress((void**)&p_xtl, g_xtl);
    cudaGetSymbolAddress((void**)&p_Sh,  g_Sh);
    cudaGetSymbolAddress((void**)&p_Sl,  g_Sl);
    cudaGetSymbolAddress((void**)&p_H1,  g_H1);
    cudaGetSymbolAddress((void**)&p_Th,  g_Th);
    cudaGetSymbolAddress((void**)&p_Tl,  g_Tl);
    cudaGetSymbolAddress((void**)&p_or,  g_or);
    cudaGetSymbolAddress((void**)&p_W1h, g_W1h);
    cudaGetSymbolAddress((void**)&p_W1l, g_W1l);
    cudaGetSymbolAddress((void**)&p_W2h, g_W2h);
    cudaGetSymbolAddress((void**)&p_W2l, g_W2l);
    cudaGetSymbolAddress((void**)&p_Wlh, g_Wlh);
    cudaGetSymbolAddress((void**)&p_Wll, g_Wll);

    cudaFuncSetAttribute(k_gmm<0>, cudaFuncAttributeMaxDynamicSharedMemorySize, SMEM_GMM);
    cudaFuncSetAttribute(k_gmm<1>, cudaFuncAttributeMaxDynamicSharedMemorySize, SMEM_GMM);
    cudaFuncSetAttribute(k_gmm<2>, cudaFuncAttributeMaxDynamicSharedMemorySize, SMEM_GMM);

    // input transpose + split
    k_tin<<<dim3(NN / 32, CIN / 32, B_), dim3(32, 8)>>>(x);
    // weight transposes + splits
    k_wt<<<dim3(HIDF / 32, CIN / 32), dim3(32, 8)>>>(W1, p_W1h, p_W1l, HIDF);
    k_wt<<<dim3(OUTF / 32, CIN / 32), dim3(32, 8)>>>(W2, p_W2h, p_W2l, OUTF);
    k_wt<<<dim3(OUTF / 32, CIN / 32), dim3(32, 8)>>>(Wl, p_Wlh, p_Wll, OUTF);
    // S = stencil(xt)
    k_st<<<dim3(NN, B_), CIN / 4>>>((const float4*)p_xt, p_Sh, p_Sl);
    // H1e = relu(S@W1 + b1) + xt
    k_gmm<0><<<dim3(HIDF / BNt, MROWS / BMt), 256, SMEM_GMM>>>(
        p_Sh, p_Sl, p_W1h, p_W1l, b1, p_xt, p_H1, HIDF);
    // T = stencil(H1e)
    k_st<<<dim3(NN, B_), HIDF / 4>>>((const float4*)p_H1, p_Th, p_Tl);
    // origin = xt@Wl + bl   [m][OUTF]
    k_gmm<1><<<dim3(OUTF / BNt, MROWS / BMt), 256, SMEM_GMM>>>(
        p_xth, p_xtl, p_Wlh, p_Wll, bl, nullptr, p_or, OUTF);
    // out = (T@W2 + b2) * origin, scattered to [B, OUT, H, W]
    k_gmm<2><<<dim3(OUTF / BNt, MROWS / BMt), 256, SMEM_GMM>>>(
        p_Th, p_Tl, p_W2h, p_W2l, b2, p_or, out, OUTF);
}

// round 7
// speedup vs baseline: 2.1250x; 1.0799x over previous
#include <cuda_runtime.h>
#include <cuda_bf16.h>
#include <cstdint>

#define B_    4
#define CIN   1536
#define HIDF  1536
#define OUTF  512
#define HH    64
#define NN    4096
#define MROWS (B_ * NN)      // 16384

// ---------------- GEMM tile config (HMMA mma.sync path) ---------------------
#define BMt 128
#define BNt 256
#define BKt 32
#define NKT (CIN / BKt)          // 48
#define ROWPITCH 80              // 32 bf16 = 64B data, padded to 80B
#define OFF_AH 0
#define OFF_AL (128 * ROWPITCH)              // 10240
#define OFF_BH (2 * 128 * ROWPITCH)          // 20480
#define OFF_BL (OFF_BH + 256 * ROWPITCH)     // 40960
#define STG_BYTES (OFF_BL + 256 * ROWPITCH)  // 61440
#define NSTAGE 3
#define SMEM_GMM (NSTAGE * STG_BYTES)        // 184320

// ---------------- scratch ----------------------------------------------------
__device__ float         g_xt [(size_t)MROWS * CIN];
__device__ __nv_bfloat16 g_xth[(size_t)MROWS * CIN];
__device__ __nv_bfloat16 g_xtl[(size_t)MROWS * CIN];
__device__ __nv_bfloat16 g_Sh [(size_t)MROWS * CIN];
__device__ __nv_bfloat16 g_Sl [(size_t)MROWS * CIN];
__device__ float         g_H1 [(size_t)MROWS * HIDF];
__device__ __nv_bfloat16 g_Th [(size_t)MROWS * HIDF];
__device__ __nv_bfloat16 g_Tl [(size_t)MROWS * HIDF];
__device__ float         g_or [(size_t)MROWS * OUTF];
__device__ __nv_bfloat16 g_W1h[(size_t)HIDF * CIN];
__device__ __nv_bfloat16 g_W1l[(size_t)HIDF * CIN];
__device__ __nv_bfloat16 g_W2h[(size_t)OUTF * CIN];
__device__ __nv_bfloat16 g_W2l[(size_t)OUTF * CIN];
__device__ __nv_bfloat16 g_Wlh[(size_t)OUTF * CIN];
__device__ __nv_bfloat16 g_Wll[(size_t)OUTF * CIN];

// ---------------- helpers ----------------------------------------------------
__device__ __forceinline__ uint32_t smem_u32(const void* p) {
    uint32_t a;
    asm("{ .reg .u64 t; cvta.to.shared.u64 t, %1; cvt.u32.u64 %0, t; }" : "=r"(a) : "l"(p));
    return a;
}
__device__ __forceinline__ void cp16(uint32_t dst, const void* src) {
    asm volatile("cp.async.cg.shared.global [%0], [%1], 16;" :: "r"(dst), "l"(src));
}
#define CP_COMMIT() asm volatile("cp.async.commit_group;" ::: "memory")
#define CP_WAIT1()  asm volatile("cp.async.wait_group 1;" ::: "memory")
#define CP_WAIT0()  asm volatile("cp.async.wait_group 0;" ::: "memory")

#define LDSM4(r0, r1, r2, r3, a)                                           \
    asm volatile("ldmatrix.sync.aligned.m8n8.x4.shared.b16 {%0,%1,%2,%3}, [%4];" \
                 : "=r"(r0), "=r"(r1), "=r"(r2), "=r"(r3) : "r"(a))

#define MMA(d, a, b0, b1)                                                  \
    asm volatile("mma.sync.aligned.m16n8k16.row.col.f32.bf16.bf16.f32 "    \
                 "{%0,%1,%2,%3},{%4,%5,%6,%7},{%8,%9},{%0,%1,%2,%3};"      \
                 : "+f"((d)[0]), "+f"((d)[1]), "+f"((d)[2]), "+f"((d)[3])  \
                 : "r"((a)[0]), "r"((a)[1]), "r"((a)[2]), "r"((a)[3]),     \
                   "r"(b0), "r"(b1))

__device__ __forceinline__ void split1(float v, __nv_bfloat16& h, __nv_bfloat16& l) {
    h = __float2bfloat16_rn(v);
    l = __float2bfloat16_rn(v - __bfloat162float(h));
}

// ---------------- transpose in: x [B,C,N] -> xt fp32 + hi/lo ----------------
__global__ void k_tin(const float* __restrict__ x) {
    __shared__ float tile[32][33];
    int b = blockIdx.z, n0 = blockIdx.x << 5, c0 = blockIdx.y << 5;
    int tx = threadIdx.x, ty = threadIdx.y;
    const float* xb = x + (size_t)b * CIN * NN;
#pragma unroll
    for (int i = ty; i < 32; i += 8)
        tile[i][tx] = xb[(size_t)(c0 + i) * NN + (n0 + tx)];
    __syncthreads();
    size_t ob = (size_t)b * NN * CIN;
#pragma unroll
    for (int i = ty; i < 32; i += 8) {
        float v = tile[tx][i];
        size_t idx = ob + (size_t)(n0 + i) * CIN + (c0 + tx);
        g_xt[idx] = v;
        __nv_bfloat16 h, l; split1(v, h, l);
        g_xth[idx] = h; g_xtl[idx] = l;
    }
}

// ---------------- weight prep: W [K,Nc] -> Wt hi/lo [Nc,K] ------------------
__global__ void k_wt(const float* __restrict__ W, __nv_bfloat16* __restrict__ oh,
                     __nv_bfloat16* __restrict__ ol, int Nc) {
    __shared__ float tile[32][33];
    int n0 = blockIdx.x << 5, k0 = blockIdx.y << 5;
    int tx = threadIdx.x, ty = threadIdx.y;
#pragma unroll
    for (int i = ty; i < 32; i += 8)
        tile[i][tx] = W[(size_t)(k0 + i) * Nc + (n0 + tx)];
    __syncthreads();
#pragma unroll
    for (int i = ty; i < 32; i += 8) {
        float v = tile[tx][i];
        size_t idx = (size_t)(n0 + i) * CIN + (k0 + tx);
        __nv_bfloat16 h, l; split1(v, h, l);
        oh[idx] = h; ol[idx] = l;
    }
}

// ---------------- 5-point GCN stencil -> bf16 hi/lo -------------------------
__device__ __forceinline__ int degat(int r, int c) {
    return 1 + (r > 0) + (r < HH - 1) + (c > 0) + (c < HH - 1);
}

__global__ void k_st(const float4* __restrict__ in,
                     __nv_bfloat16* __restrict__ oh, __nv_bfloat16* __restrict__ ol) {
    const int C4 = CIN / 4;
    int n = blockIdx.x, b = blockIdx.y, t = threadIdx.x;
    int r = n >> 6, c = n & 63;
    int dg = degat(r, c);
    size_t base = (size_t)b * NN * C4;
    const float4* pin = in + base;

    float4 v = pin[(size_t)n * C4 + t];
    float wc = 1.0f / (float)dg;
    float4 acc = make_float4(v.x * wc, v.y * wc, v.z * wc, v.w * wc);
#define NBR(nm, dr, dc)                                      \
    {                                                        \
        int dn = degat(r + (dr), c + (dc));                  \
        float w = rsqrtf((float)(dg * dn));                  \
        float4 u = pin[(size_t)(nm) * C4 + t];               \
        acc.x += u.x * w; acc.y += u.y * w;                  \
        acc.z += u.z * w; acc.w += u.w * w;                  \
    }
    if (r > 0)  NBR(n - 64, -1, 0);
    if (r < 63) NBR(n + 64, +1, 0);
    if (c > 0)  NBR(n - 1, 0, -1);
    if (c < 63) NBR(n + 1, 0, +1);
#undef NBR
    __nv_bfloat16 hx, lx, hy, ly, hz, lz, hw, lw;
    split1(acc.x, hx, lx); split1(acc.y, hy, ly);
    split1(acc.z, hz, lz); split1(acc.w, hw, lw);
    uint32_t h01 = ((uint32_t)__bfloat16_as_ushort(hy) << 16) | __bfloat16_as_ushort(hx);
    uint32_t h23 = ((uint32_t)__bfloat16_as_ushort(hw) << 16) | __bfloat16_as_ushort(hz);
    uint32_t l01 = ((uint32_t)__bfloat16_as_ushort(ly) << 16) | __bfloat16_as_ushort(lx);
    uint32_t l23 = ((uint32_t)__bfloat16_as_ushort(lw) << 16) | __bfloat16_as_ushort(lz);
    size_t idx = base + (size_t)n * C4 + t;
    ((uint2*)oh)[idx] = make_uint2(h01, h23);
    ((uint2*)ol)[idx] = make_uint2(l01, l23);
}

// ---------------- HMMA split-bf16 GEMM, CTA 128x256, warp 64x64 -------------
// D[m,n] = sum_k A[m,k]*B[n,k], via AhBh + AlBh + AhBl, fp32 reg accum.
// EPI 0: C[m][Nc] = relu(acc+bias[n]) + aux[m][Nc]
// EPI 1: C[m][Nc] = acc + bias[n]
// EPI 2: out[(b*OUTF+n)*NN + (m&4095)] = (acc+bias[n]) * aux[m][Nc]
template <int EPI>
__global__ __launch_bounds__(256, 1) void k_gmm(
    const __nv_bfloat16* __restrict__ Ah, const __nv_bfloat16* __restrict__ Al,
    const __nv_bfloat16* __restrict__ Bh, const __nv_bfloat16* __restrict__ Bl,
    const float* __restrict__ bias, const float* __restrict__ aux,
    float* __restrict__ C, int Nc)
{
    extern __shared__ char smem[];
    uint32_t sb = smem_u32(smem);
    int tid = threadIdx.x, wid = tid >> 5, lane = tid & 31;
    int bm = blockIdx.y * BMt, bn = blockIdx.x * BNt;

    // ---- producer addressing: 12 x 16B cp.async per thread per stage ----
    const __nv_bfloat16* psrc[12];
    uint32_t pdst[12];
#pragma unroll
    for (int j = 0; j < 12; j++) {
        int c = tid + j * 256;           // 0..3071
        const __nv_bfloat16* base;
        int row, r0;
        uint32_t off;
        if (c < 512)       { base = Ah; row = c >> 2;          r0 = bm; off = OFF_AH; }
        else if (c < 1024) { base = Al; row = (c - 512) >> 2;  r0 = bm; off = OFF_AL; }
        else if (c < 2048) { base = Bh; row = (c - 1024) >> 2; r0 = bn; off = OFF_BH; }
        else               { base = Bl; row = (c - 2048) >> 2; r0 = bn; off = OFF_BL; }
        int sl = c & 3;
        psrc[j] = base + (size_t)(r0 + row) * CIN + sl * 8;
        pdst[j] = off + (uint32_t)(row * ROWPITCH + sl * 16);
    }

#define ISSUE(stg, kt)                                                     \
    {                                                                      \
        uint32_t stb_ = sb + (stg) * STG_BYTES;                            \
        _Pragma("unroll")                                                  \
        for (int j = 0; j < 12; j++)                                       \
            cp16(stb_ + pdst[j], psrc[j] + (kt) * BKt);                    \
        CP_COMMIT();                                                       \
    }

    ISSUE(0, 0);
    ISSUE(1, 1);

    // ---- consumer addressing: warp (wm, wn) owns 64x64 ----
    int wm = wid & 1, wn = wid >> 1;
    uint32_t a_base = (uint32_t)((wm * 64 + (lane & 15)) * ROWPITCH + ((lane >> 4) << 4));
    uint32_t b_base = (uint32_t)(OFF_BH +
        (wn * 64 + ((lane & 7) | ((lane >> 4) << 3))) * ROWPITCH + (((lane >> 3) & 1) << 4));

    float acc[4][8][4];
#pragma unroll
    for (int mi = 0; mi < 4; mi++)
#pragma unroll
        for (int nt = 0; nt < 8; nt++)
#pragma unroll
            for (int q = 0; q < 4; q++) acc[mi][nt][q] = 0.f;

    for (int kt = 0; kt < NKT; kt++) {
        if (kt + 1 < NKT) CP_WAIT1(); else CP_WAIT0();
        __syncthreads();
        if (kt + 2 < NKT) ISSUE((kt + 2) % NSTAGE, kt + 2);

        uint32_t st = sb + (kt % NSTAGE) * STG_BYTES;
#pragma unroll
        for (int ks = 0; ks < 2; ks++) {
            uint32_t ah[4][4], al[4][4], bh[8][2];
            uint32_t ak = st + a_base + ks * 32;
#pragma unroll
            for (int mi = 0; mi < 4; mi++) {
                LDSM4(ah[mi][0], ah[mi][1], ah[mi][2], ah[mi][3], ak + mi * (16 * ROWPITCH));
                LDSM4(al[mi][0], al[mi][1], al[mi][2], al[mi][3],
                      ak + (OFF_AL - OFF_AH) + mi * (16 * ROWPITCH));
            }
            uint32_t bk = st + b_base + ks * 32;
#pragma unroll
            for (int j = 0; j < 4; j++) {
                uint32_t r0, r1, r2, r3;
                LDSM4(r0, r1, r2, r3, bk + j * (16 * ROWPITCH));
                bh[j * 2][0] = r0;     bh[j * 2][1] = r1;
                bh[j * 2 + 1][0] = r2; bh[j * 2 + 1][1] = r3;
            }
            // main product + A-low correction (bh live, al dies after)
#pragma unroll
            for (int mi = 0; mi < 4; mi++)
#pragma unroll
                for (int nt = 0; nt < 8; nt++)
                    MMA(acc[mi][nt], ah[mi], bh[nt][0], bh[nt][1]);
#pragma unroll
            for (int mi = 0; mi < 4; mi++)
#pragma unroll
                for (int nt = 0; nt < 8; nt++)
                    MMA(acc[mi][nt], al[mi], bh[nt][0], bh[nt][1]);
            // B-low correction (reuse bh registers for bl)
            uint32_t bl[8][2];
#pragma unroll
            for (int j = 0; j < 4; j++) {
                uint32_t r0, r1, r2, r3;
                LDSM4(r0, r1, r2, r3, bk + (OFF_BL - OFF_BH) + j * (16 * ROWPITCH));
                bl[j * 2][0] = r0;     bl[j * 2][1] = r1;
                bl[j * 2 + 1][0] = r2; bl[j * 2 + 1][1] = r3;
            }
#pragma unroll
            for (int mi = 0; mi < 4; mi++)
#pragma unroll
                for (int nt = 0; nt < 8; nt++)
                    MMA(acc[mi][nt], ah[mi], bl[nt][0], bl[nt][1]);
        }
    }

    // ---- epilogue (register fragments, fused) ----
#pragma unroll
    for (int mi = 0; mi < 4; mi++)
#pragma unroll
        for (int nt = 0; nt < 8; nt++) {
            int m0 = bm + wm * 64 + mi * 16 + (lane >> 2);
            int n0 = bn + wn * 64 + nt * 8 + ((lane & 3) << 1);
            const float* a4 = acc[mi][nt];
            float bs0 = __ldg(&bias[n0]), bs1 = __ldg(&bias[n0 + 1]);
            size_t i0 = (size_t)m0 * Nc + n0;
            size_t i1 = (size_t)(m0 + 8) * Nc + n0;
            if (EPI == 0) {
                float2 x0 = *(const float2*)(aux + i0);
                float2 x1 = *(const float2*)(aux + i1);
                *(float2*)(C + i0) = make_float2(fmaxf(a4[0] + bs0, 0.f) + x0.x,
                                                 fmaxf(a4[1] + bs1, 0.f) + x0.y);
                *(float2*)(C + i1) = make_float2(fmaxf(a4[2] + bs0, 0.f) + x1.x,
                                                 fmaxf(a4[3] + bs1, 0.f) + x1.y);
            } else if (EPI == 1) {
                *(float2*)(C + i0) = make_float2(a4[0] + bs0, a4[1] + bs1);
                *(float2*)(C + i1) = make_float2(a4[2] + bs0, a4[3] + bs1);
            } else {
                float2 g0 = *(const float2*)(aux + i0);
                float2 g1 = *(const float2*)(aux + i1);
                int b0 = m0 >> 12, nn0 = m0 & (NN - 1);
                int nn1 = nn0 + 8;
                C[((size_t)(b0 * OUTF + n0)) * NN + nn0]     = (a4[0] + bs0) * g0.x;
                C[((size_t)(b0 * OUTF + n0 + 1)) * NN + nn0] = (a4[1] + bs1) * g0.y;
                C[((size_t)(b0 * OUTF + n0)) * NN + nn1]     = (a4[2] + bs0) * g1.x;
                C[((size_t)(b0 * OUTF + n0 + 1)) * NN + nn1] = (a4[3] + bs1) * g1.y;
            }
        }
#undef ISSUE
}

// ---------------- launch -----------------------------------------------------
extern "C" void kernel_launch(void* const* d_in, const int* in_sizes, int n_in,
                              void* d_out, int out_size) {
    const float* x  = (const float*)d_in[0];
    const float* W1 = (const float*)d_in[1];
    const float* b1 = (const float*)d_in[2];
    const float* W2 = (const float*)d_in[3];
    const float* b2 = (const float*)d_in[4];
    const float* Wl = (const float*)d_in[5];
    const float* bl = (const float*)d_in[6];
    float* out = (float*)d_out;

    float *p_xt, *p_H1, *p_or;
    __nv_bfloat16 *p_xth, *p_xtl, *p_Sh, *p_Sl, *p_Th, *p_Tl;
    __nv_bfloat16 *p_W1h, *p_W1l, *p_W2h, *p_W2l, *p_Wlh, *p_Wll;
    cudaGetSymbolAddress((void**)&p_xt,  g_xt);
    cudaGetSymbolAddress((void**)&p_xth, g_xth);
    cudaGetSymbolAddress((void**)&p_xtl, g_xtl);
    cudaGetSymbolAddress((void**)&p_Sh,  g_Sh);
    cudaGetSymbolAddress((void**)&p_Sl,  g_Sl);
    cudaGetSymbolAddress((void**)&p_H1,  g_H1);
    cudaGetSymbolAddress((void**)&p_Th,  g_Th);
    cudaGetSymbolAddress((void**)&p_Tl,  g_Tl);
    cudaGetSymbolAddress((void**)&p_or,  g_or);
    cudaGetSymbolAddress((void**)&p_W1h, g_W1h);
    cudaGetSymbolAddress((void**)&p_W1l, g_W1l);
    cudaGetSymbolAddress((void**)&p_W2h, g_W2h);
    cudaGetSymbolAddress((void**)&p_W2l, g_W2l);
    cudaGetSymbolAddress((void**)&p_Wlh, g_Wlh);
    cudaGetSymbolAddress((void**)&p_Wll, g_Wll);

    cudaFuncSetAttribute(k_gmm<0>, cudaFuncAttributeMaxDynamicSharedMemorySize, SMEM_GMM);
    cudaFuncSetAttribute(k_gmm<1>, cudaFuncAttributeMaxDynamicSharedMemorySize, SMEM_GMM);
    cudaFuncSetAttribute(k_gmm<2>, cudaFuncAttributeMaxDynamicSharedMemorySize, SMEM_GMM);

    // input transpose + split
    k_tin<<<dim3(NN / 32, CIN / 32, B_), dim3(32, 8)>>>(x);
    // weight transposes + splits
    k_wt<<<dim3(HIDF / 32, CIN / 32), dim3(32, 8)>>>(W1, p_W1h, p_W1l, HIDF);
    k_wt<<<dim3(OUTF / 32, CIN / 32), dim3(32, 8)>>>(W2, p_W2h, p_W2l, OUTF);
    k_wt<<<dim3(OUTF / 32, CIN / 32), dim3(32, 8)>>>(Wl, p_Wlh, p_Wll, OUTF);
    // S = stencil(xt)
    k_st<<<dim3(NN, B_), CIN / 4>>>((const float4*)p_xt, p_Sh, p_Sl);
    // H1e = relu(S@W1 + b1) + xt
    k_gmm<0><<<dim3(HIDF / BNt, MROWS / BMt), 256, SMEM_GMM>>>(
        p_Sh, p_Sl, p_W1h, p_W1l, b1, p_xt, p_H1, HIDF);
    // T = stencil(H1e)
    k_st<<<dim3(NN, B_), HIDF / 4>>>((const float4*)p_H1, p_Th, p_Tl);
    // origin = xt@Wl + bl
    k_gmm<1><<<dim3(OUTF / BNt, MROWS / BMt), 256, SMEM_GMM>>>(
        p_xth, p_xtl, p_Wlh, p_Wll, bl, nullptr, p_or, OUTF);
    // out = (T@W2 + b2) * origin, scattered to [B, OUT, H, W]
    k_gmm<2><<<dim3(OUTF / BNt, MROWS / BMt), 256, SMEM_GMM>>>(
        p_Th, p_Tl, p_W2h, p_W2l, b2, p_or, out, OUTF);
}